// round 7
// baseline (speedup 1.0000x reference)
#include <cuda_runtime.h>

// B3-spline UWT (à trous), J=3, fused single kernel.
// x (8,1024,1024) f32 -> out (8,4,1024,1024) = [w1,w2,w3,c3]
//
// One CTA = 64x64 output tile, 96x96 working grid, PIT=96 (72 KB, 3 CTAs/SM,
// NT=256). Conflict-free smem law: lanes contiguous, stride == access width.
// Level 1 (interior tiles): h+w fused, reads x straight from global, writes c1
// to A, emits w1 — no smem temp, no extra barrier. Levels 2/3: split vertical
// (register-amortized) + horizontal (emit-fused) passes; c_j overwrites
// c_{j-1} in place (same-item read-before-write).

namespace {

constexpr int HW   = 1024;
constexpr int Sg   = 96;
constexpr int PIT  = 96;
constexpr int CEN  = 16;
constexpr int TILE = 64;
constexpr int NT   = 256;
constexpr float W0 = 0.0625f, W1 = 0.25f, W2 = 0.375f;

__device__ __forceinline__ int refl(int i) {
    if (i < 0) i = -i;
    if (i >= HW) i = 2 * HW - 2 - i;
    return i;
}

__device__ __forceinline__ float2 ld2(const float* p) {
    return *reinterpret_cast<const float2*>(p);
}
__device__ __forceinline__ float4 ld4(const float* p) {
    return *reinterpret_cast<const float4*>(p);
}

// Fused level-1 (d=1) for interior tiles: vertical+horizontal in registers,
// source = global x (row pitch HW). Item = 1 row x 4 cols; window = 8 cols
// (x-2..x+5) loaded as ld2 + ld4 + ld2 (all naturally aligned), 5 rows.
// Writes c1 to A rows/cols 4..91; center items emit w1 = x - c1.
__device__ __forceinline__ void fused_l1(const float* __restrict__ gsrc,
                                         const float* __restrict__ xb,
                                         float* __restrict__ A,
                                         float* __restrict__ ow,
                                         int ty0, int tx0, int tid) {
    const float wt[5] = {W0, W1, W2, W1, W0};
    const int items = 88 * 22;  // rows 4..91, col groups x = 4..88 step 4
    for (int it = tid; it < items; it += NT) {
        const int g = it % 22;
        const int y = 4 + it / 22;
        const int x = 4 + 4 * g;
        const float* p = gsrc + (size_t)(y - 2) * HW + (x - 2);
        float acc[8];
#pragma unroll
        for (int i = 0; i < 8; ++i) acc[i] = 0.f;
#pragma unroll
        for (int r = 0; r < 5; ++r) {
            const float w = wt[r];
            const float* rp = p + (size_t)r * HW;
            const float2 a = ld2(rp);
            const float4 m = ld4(rp + 2);
            const float2 b = ld2(rp + 6);
            acc[0] += w * a.x; acc[1] += w * a.y;
            acc[2] += w * m.x; acc[3] += w * m.y;
            acc[4] += w * m.z; acc[5] += w * m.w;
            acc[6] += w * b.x; acc[7] += w * b.y;
        }
        float o[4];
#pragma unroll
        for (int i = 0; i < 4; ++i)
            o[i] = W0 * (acc[i] + acc[i + 4]) + W1 * (acc[i + 1] + acc[i + 3]) +
                   W2 * acc[i + 2];
        *reinterpret_cast<float4*>(A + y * PIT + x) =
            make_float4(o[0], o[1], o[2], o[3]);
        if (y >= CEN && y < CEN + TILE && x >= CEN && x < CEN + TILE) {
            const size_t go = (size_t)(ty0 + y - CEN) * HW + (tx0 + x - CEN);
            const float4 pv = ld4(xb + go);
            *reinterpret_cast<float4*>(ow + go) =
                make_float4(pv.x - o[0], pv.y - o[1], pv.z - o[2], pv.w - o[3]);
        }
    }
}

// Vertical 5-tap conv, dilation D, float2 lanes, RPB rows per item.
template <int D, int RPB, int SPIT, int NCP>
__device__ __forceinline__ void hconv2(const float* __restrict__ src,
                                       float* __restrict__ dst,
                                       int r0, int nrb, int c0, int tid) {
    const int items = nrb * NCP;
    for (int it = tid; it < items; it += NT) {
        const int c  = c0 + 2 * (it % NCP);
        const int y0 = r0 + (it / NCP) * RPB;
        const float* sp = src + (y0 - 2 * D) * SPIT + c;
        float2 acc[RPB];
#pragma unroll
        for (int i = 0; i < RPB; ++i) acc[i] = make_float2(0.f, 0.f);
#pragma unroll
        for (int rr = 0; rr < RPB + 4 * D; ++rr) {
            const float2 v = ld2(sp + rr * SPIT);
#pragma unroll
            for (int i = 0; i < RPB; ++i) {
                const int t = rr - i;
                if (t >= 0 && t <= 4 * D && (t % D) == 0) {
                    const float w = (t == 0 || t == 4 * D) ? W0
                                  : (t == D || t == 3 * D) ? W1 : W2;
                    acc[i].x += w * v.x; acc[i].y += w * v.y;
                }
            }
        }
        float* dp = dst + y0 * PIT + c;
#pragma unroll
        for (int i = 0; i < RPB; ++i)
            *reinterpret_cast<float2*>(dp + i * PIT) = acc[i];
    }
}

// Horizontal 5-tap conv, dilation D, float4 items (4 outputs per lane).
template <int D, bool STOREC, bool EMITC, int NCG>
__device__ __forceinline__ void wconv(const float* __restrict__ Ybuf,
                                      float* Abuf,
                                      int r0, int nrows, int cg0,
                                      float* __restrict__ owp,
                                      float* __restrict__ ocp,
                                      int ty0, int tx0, int tid) {
    constexpr int LOFF = (D == 4) ? 8 : 4;            // floats before x (aligned)
    constexpr int NLD  = (LOFF + 4 + 2 * D + 3) / 4;  // float4 loads
    constexpr int B0   = LOFF - 2 * D;                // buf idx of x-2D
    const int items = nrows * NCG;
    for (int it = tid; it < items; it += NT) {
        const int x  = (cg0 + it % NCG) * 4;
        const int y  = r0 + it / NCG;
        const float* row = Ybuf + y * PIT + x - LOFF;
        float buf[NLD * 4];
#pragma unroll
        for (int j = 0; j < NLD; ++j) {
            const float4 v = ld4(row + 4 * j);
            buf[4 * j] = v.x; buf[4 * j + 1] = v.y;
            buf[4 * j + 2] = v.z; buf[4 * j + 3] = v.w;
        }
        float o[4];
#pragma unroll
        for (int i = 0; i < 4; ++i)
            o[i] = W0 * (buf[B0 + i] + buf[B0 + i + 4 * D]) +
                   W1 * (buf[B0 + i + D] + buf[B0 + i + 3 * D]) +
                   W2 * buf[B0 + i + 2 * D];

        const bool cen = (y >= CEN) & (y < CEN + TILE) &
                         (x >= CEN) & (x < CEN + TILE);
        if (cen) {
            const size_t go = (size_t)(ty0 + y - CEN) * HW + (tx0 + x - CEN);
            const float4 pv = ld4(Abuf + y * PIT + x);  // prev coeff
            *reinterpret_cast<float4*>(owp + go) =
                make_float4(pv.x - o[0], pv.y - o[1], pv.z - o[2], pv.w - o[3]);
            if (EMITC)
                *reinterpret_cast<float4*>(ocp + go) =
                    make_float4(o[0], o[1], o[2], o[3]);
        }
        if (STOREC)
            *reinterpret_cast<float4*>(Abuf + y * PIT + x) =
                make_float4(o[0], o[1], o[2], o[3]);
    }
}

}  // namespace

extern __shared__ float g_smem[];

__global__ void __launch_bounds__(NT, 3)
uwt_kernel(const float* __restrict__ x, float* __restrict__ out) {
    float* A = g_smem;              // coeff plane c_j (in-place per level)
    float* Y = g_smem + Sg * PIT;   // vertical-conv temp (levels 2,3)

    const int tid = threadIdx.x;
    const int tx0 = (blockIdx.x & 15) * TILE;
    const int ty0 = (blockIdx.x >> 4) * TILE;
    const float* xb = x + (size_t)blockIdx.y * HW * HW;
    float* ob = out + (size_t)blockIdx.y * 4 * HW * HW;

    const bool interior = (tx0 > 0) & (tx0 < HW - TILE) &
                          (ty0 > 0) & (ty0 < HW - TILE);

    if (interior) {
        // Level 1 fused (global -> c1 in A, emit w1). No Y plane, no h1 phase.
        const float* gsrc = xb + (size_t)(ty0 - CEN) * HW + (tx0 - CEN);
        fused_l1(gsrc, xb, A, ob, ty0, tx0, tid);
    } else {
        // Edge tile: stage reflected c0 into A, split h1/w1 from smem.
        for (int i = tid; i < Sg * Sg; i += NT) {
            const int y = i / Sg, xx = i - y * Sg;
            A[y * PIT + xx] =
                xb[(size_t)refl(ty0 - CEN + y) * HW + refl(tx0 - CEN + xx)];
        }
        __syncthreads();
        hconv2<1, 8, PIT, 48>(A, Y, 4, 11, 0, tid);
        __syncthreads();
        wconv<1, true, false, 22>(Y, A, 4, 88, 1, ob, nullptr, ty0, tx0, tid);
    }
    __syncthreads();

    // Level 2 (d=2): h2 out rows 8..87 x cols 4..91.
    hconv2<2, 16, PIT, 44>(A, Y, 8, 5, 4, tid);
    __syncthreads();
    // w2: c2 -> A on rows 8..87 x cols 8..87; emit w2 = c1 - c2.
    wconv<2, true, false, 20>(Y, A, 8, 80, 2,
                              ob + (size_t)HW * HW, nullptr, ty0, tx0, tid);
    __syncthreads();

    // Level 3 (d=4): h3 out rows 16..79 x cols 8..87.
    hconv2<4, 16, PIT, 40>(A, Y, 16, 4, 8, tid);
    __syncthreads();
    // w3: center only; emit w3 = c2 - c3 and c3. No smem store.
    wconv<4, false, true, 16>(Y, A, 16, 64, 4,
                              ob + 2 * (size_t)HW * HW,
                              ob + 3 * (size_t)HW * HW, ty0, tx0, tid);
}

extern "C" void kernel_launch(void* const* d_in, const int* in_sizes, int n_in,
                              void* d_out, int out_size) {
    const float* x = (const float*)d_in[0];
    float* out = (float*)d_out;
    const int smemBytes = 2 * Sg * PIT * (int)sizeof(float);  // 73728 B
    cudaFuncSetAttribute(uwt_kernel, cudaFuncAttributeMaxDynamicSharedMemorySize,
                         smemBytes);
    dim3 grid(256, 8);
    uwt_kernel<<<grid, NT, smemBytes>>>(x, out);
}

// round 8
// speedup vs baseline: 1.1575x; 1.1575x over previous
#include <cuda_runtime.h>

// B3-spline UWT (à trous), J=3, fused single kernel.
// x (8,1024,1024) f32 -> out (8,4,1024,1024) = [w1,w2,w3,c3]
//
// One CTA = 64x64 output tile, 96x96 working grid, PIT=96 (72 KB, 3 CTAs/SM,
// NT=256). Conflict-free smem law: (a) lanes contiguous, lane stride == access
// width; (b) items-per-row padded to the phase multiple (16 for float2 LDS.64,
// 8 for float4 LDS.128) so no memory phase straddles a row boundary.
// Emits fused into W-conv passes; c_j overwrites c_{j-1} in place.

namespace {

constexpr int HW   = 1024;
constexpr int Sg   = 96;
constexpr int PIT  = 96;
constexpr int CEN  = 16;
constexpr int TILE = 64;
constexpr int NT   = 256;
constexpr float W0 = 0.0625f, W1 = 0.25f, W2 = 0.375f;

__device__ __forceinline__ int refl(int i) {
    if (i < 0) i = -i;
    if (i >= HW) i = 2 * HW - 2 - i;
    return i;
}

__device__ __forceinline__ float2 ld2(const float* p) {
    return *reinterpret_cast<const float2*>(p);
}
__device__ __forceinline__ float4 ld4(const float* p) {
    return *reinterpret_cast<const float4*>(p);
}

// Vertical 5-tap conv, dilation D, float2 lanes, RPB rows per item.
// NCP = live col-pairs per row; NCPP = padded pairs per row (multiple of 16).
template <int D, int RPB, int SPIT, int NCP, int NCPP>
__device__ __forceinline__ void hconv2(const float* __restrict__ src,
                                       float* __restrict__ dst,
                                       int r0, int nrb, int c0, int tid) {
    const int items = nrb * NCPP;
    for (int it = tid; it < items; it += NT) {
        const int g = it % NCPP;
        if (g >= NCP) continue;
        const int c  = c0 + 2 * g;
        const int y0 = r0 + (it / NCPP) * RPB;
        const float* sp = src + (y0 - 2 * D) * SPIT + c;
        float2 acc[RPB];
#pragma unroll
        for (int i = 0; i < RPB; ++i) acc[i] = make_float2(0.f, 0.f);
#pragma unroll
        for (int rr = 0; rr < RPB + 4 * D; ++rr) {
            const float2 v = ld2(sp + rr * SPIT);
#pragma unroll
            for (int i = 0; i < RPB; ++i) {
                const int t = rr - i;
                if (t >= 0 && t <= 4 * D && (t % D) == 0) {
                    const float w = (t == 0 || t == 4 * D) ? W0
                                  : (t == D || t == 3 * D) ? W1 : W2;
                    acc[i].x += w * v.x; acc[i].y += w * v.y;
                }
            }
        }
        float* dp = dst + y0 * PIT + c;
#pragma unroll
        for (int i = 0; i < RPB; ++i)
            *reinterpret_cast<float2*>(dp + i * PIT) = acc[i];
    }
}

// Horizontal 5-tap conv, dilation D, float4 items (4 outputs per lane).
// NCG = live col-groups per row; NCGP = padded groups (multiple of 8).
template <int D, bool STOREC, bool EMITC, bool PREVG, int NCG, int NCGP>
__device__ __forceinline__ void wconv(const float* __restrict__ Ybuf,
                                      float* Abuf,
                                      int r0, int nrows, int cg0,
                                      const float* __restrict__ prevG,
                                      float* __restrict__ owp,
                                      float* __restrict__ ocp,
                                      int ty0, int tx0, int tid) {
    constexpr int LOFF = (D == 4) ? 8 : 4;            // floats before x (aligned)
    constexpr int NLD  = (LOFF + 4 + 2 * D + 3) / 4;  // float4 loads
    constexpr int B0   = LOFF - 2 * D;                // buf idx of x-2D
    const int items = nrows * NCGP;
    for (int it = tid; it < items; it += NT) {
        const int g = it % NCGP;
        if (g >= NCG) continue;
        const int x  = (cg0 + g) * 4;
        const int y  = r0 + it / NCGP;
        const float* row = Ybuf + y * PIT + x - LOFF;
        float buf[NLD * 4];
#pragma unroll
        for (int j = 0; j < NLD; ++j) {
            const float4 v = ld4(row + 4 * j);
            buf[4 * j] = v.x; buf[4 * j + 1] = v.y;
            buf[4 * j + 2] = v.z; buf[4 * j + 3] = v.w;
        }
        float o[4];
#pragma unroll
        for (int i = 0; i < 4; ++i)
            o[i] = W0 * (buf[B0 + i] + buf[B0 + i + 4 * D]) +
                   W1 * (buf[B0 + i + D] + buf[B0 + i + 3 * D]) +
                   W2 * buf[B0 + i + 2 * D];

        const bool cen = (y >= CEN) & (y < CEN + TILE) &
                         (x >= CEN) & (x < CEN + TILE);
        if (cen) {
            const size_t go = (size_t)(ty0 + y - CEN) * HW + (tx0 + x - CEN);
            float4 pv;
            if (PREVG) pv = ld4(prevG + go);
            else       pv = ld4(Abuf + y * PIT + x);
            *reinterpret_cast<float4*>(owp + go) =
                make_float4(pv.x - o[0], pv.y - o[1], pv.z - o[2], pv.w - o[3]);
            if (EMITC)
                *reinterpret_cast<float4*>(ocp + go) =
                    make_float4(o[0], o[1], o[2], o[3]);
        }
        if (STOREC)
            *reinterpret_cast<float4*>(Abuf + y * PIT + x) =
                make_float4(o[0], o[1], o[2], o[3]);
    }
}

}  // namespace

extern __shared__ float g_smem[];

__global__ void __launch_bounds__(NT, 3)
uwt_kernel(const float* __restrict__ x, float* __restrict__ out) {
    float* A = g_smem;              // coeff plane c_j (in-place per level)
    float* Y = g_smem + Sg * PIT;   // vertical-conv temp

    const int tid = threadIdx.x;
    const int tx0 = (blockIdx.x & 15) * TILE;
    const int ty0 = (blockIdx.x >> 4) * TILE;
    const float* xb = x + (size_t)blockIdx.y * HW * HW;
    float* ob = out + (size_t)blockIdx.y * 4 * HW * HW;

    const bool interior = (tx0 > 0) & (tx0 < HW - TILE) &
                          (ty0 > 0) & (ty0 < HW - TILE);

    // Level 1 H-conv (d=1): out rows 4..91 x cols 0..95 (48 pairs, aligned).
    if (interior) {
        const float* src = xb + (size_t)(ty0 - CEN) * HW + (tx0 - CEN);
        hconv2<1, 8, HW, 48, 48>(src, Y, 4, 11, 0, tid);
    } else {
        for (int i = tid; i < Sg * Sg; i += NT) {
            const int y = i / Sg, xx = i - y * Sg;
            A[y * PIT + xx] =
                xb[(size_t)refl(ty0 - CEN + y) * HW + refl(tx0 - CEN + xx)];
        }
        __syncthreads();
        hconv2<1, 8, PIT, 48, 48>(A, Y, 4, 11, 0, tid);
    }
    __syncthreads();

    // W-conv 1: c1 -> A on rows 4..91 x cols 4..91 (22 live / 24 padded).
    if (interior)
        wconv<1, true, false, true, 22, 24>(Y, A, 4, 88, 1, xb, ob, nullptr,
                                            ty0, tx0, tid);
    else
        wconv<1, true, false, false, 22, 24>(Y, A, 4, 88, 1, nullptr, ob,
                                             nullptr, ty0, tx0, tid);
    __syncthreads();

    // Level 2 (d=2): h2 rows 8..87 x cols 4..91 (44 live / 48 padded pairs).
    hconv2<2, 16, PIT, 44, 48>(A, Y, 8, 5, 4, tid);
    __syncthreads();
    // w2: c2 -> A on rows 8..87 x cols 8..87 (20 live / 24 padded).
    wconv<2, true, false, false, 20, 24>(Y, A, 8, 80, 2, nullptr,
                                         ob + (size_t)HW * HW, nullptr,
                                         ty0, tx0, tid);
    __syncthreads();

    // Level 3 (d=4): h3 rows 16..79 x cols 8..87 (40 live / 48 padded pairs).
    hconv2<4, 16, PIT, 40, 48>(A, Y, 16, 4, 8, tid);
    __syncthreads();
    // w3: center only (16 groups, aligned); emit w3 = c2 - c3 and c3.
    wconv<4, false, true, false, 16, 16>(Y, A, 16, 64, 4, nullptr,
                                         ob + 2 * (size_t)HW * HW,
                                         ob + 3 * (size_t)HW * HW,
                                         ty0, tx0, tid);
}

extern "C" void kernel_launch(void* const* d_in, const int* in_sizes, int n_in,
                              void* d_out, int out_size) {
    const float* x = (const float*)d_in[0];
    float* out = (float*)d_out;
    const int smemBytes = 2 * Sg * PIT * (int)sizeof(float);  // 73728 B
    cudaFuncSetAttribute(uwt_kernel, cudaFuncAttributeMaxDynamicSharedMemorySize,
                         smemBytes);
    dim3 grid(256, 8);
    uwt_kernel<<<grid, NT, smemBytes>>>(x, out);
}